// round 9
// baseline (speedup 1.0000x reference)
#include <cuda_runtime.h>
#include <cuda_fp16.h>
#include <cstdint>

// Problem dims (fixed by the dataset)
#define BB   64
#define TT   1000
#define INN  512
#define HH   512
#define MM   (BB * TT)   // 64000

// Scratch. g_Wx is T-MAJOR: row m = t*64 + b.
__device__ float  g_Wx[MM * HH];       // 131 MB  GEMM output (t-major)
__device__ __half g_Whi[HH * INN];     // 0.5 MB  fp16-hi of W
__device__ __half g_Wlo[HH * INN];     // 0.5 MB  fp16-lo of W
__device__ int    g_cnt[MM / 128];     // 500 per-m-tile completion counters

// cp.async helpers
__device__ __forceinline__ uint32_t smem_u32(const void* p) {
    uint32_t a;
    asm("{ .reg .u64 t; cvta.to.shared.u64 t, %1; cvt.u32.u64 %0, t; }"
        : "=r"(a) : "l"(p));
    return a;
}
__device__ __forceinline__ void cp_async16(uint32_t dst, const void* src) {
    asm volatile("cp.async.cg.shared.global [%0], [%1], 16;"
                 :: "r"(dst), "l"(src));
}
__device__ __forceinline__ void cp_commit() {
    asm volatile("cp.async.commit_group;" ::: "memory");
}
__device__ __forceinline__ void cp_wait0() {
    asm volatile("cp.async.wait_group 0;" ::: "memory");
}

// ---------------------------------------------------------------------------
// Kernel 0a: W -> fp16 hi/lo split (once; tiny)
// ---------------------------------------------------------------------------
__global__ void prep_w_kernel(const float* __restrict__ W) {
    int i = blockIdx.x * blockDim.x + threadIdx.x;
    if (i < HH * INN) {
        float w   = W[i];
        __half hi = __float2half_rn(w);
        g_Whi[i]  = hi;
        g_Wlo[i]  = __float2half_rn(w - __half2float(hi));
    }
}

// Kernel 0b: zero the progress counters (every launch)
__global__ void reset_cnt_kernel() {
    if (threadIdx.x < MM / 128) g_cnt[threadIdx.x] = 0;
}

// ---------------------------------------------------------------------------
// Kernel 1: 2xFP16-split GEMM via mma.sync m16n8k16 (R7 structure, 480us).
//   T-MAJOR output: Wx row m = t*64+b  ->  A row m reads X[b= m&63][t= m>>6].
//   Epilogue publishes per-m-tile completion via fence + atomicAdd.
// ---------------------------------------------------------------------------
#define GBM 128
#define GBN 128
#define GBK 64
#define LDPH 72                       // halfs per row: conflict-free frags
#define NCHNK (INN / GBK)             // 8
#define PLANE_H (GBM * LDPH)          // 9216 halfs per plane
#define STAGE_H (4 * PLANE_H)         // Ah | Al | Bh | Bl
#define GEMM_SMEM (2 * STAGE_H * 2)   // 147456 bytes

#define MMA_F16(d, a, b)                                                      \
    asm volatile(                                                             \
        "mma.sync.aligned.m16n8k16.row.col.f32.f16.f16.f32 "                  \
        "{%0,%1,%2,%3},{%4,%5,%6,%7},{%8,%9},{%0,%1,%2,%3};"                  \
        : "+f"((d)[0]), "+f"((d)[1]), "+f"((d)[2]), "+f"((d)[3])              \
        : "r"((a)[0]), "r"((a)[1]), "r"((a)[2]), "r"((a)[3]),                 \
          "r"((b)[0]), "r"((b)[1]))

__global__ void __launch_bounds__(256, 1) gemm2fp16_kernel(
    const float* __restrict__ X)
{
    extern __shared__ __align__(16) __half smh[];
    const uint32_t smb = smem_u32(smh);

    const int tid  = threadIdx.x;
    const int lane = tid & 31;
    const int wm   = (tid >> 5) & 1;   // 2 m-warps of 64 rows
    const int wn   = tid >> 6;         // 4 n-warps of 32 cols
    const int g    = lane >> 2;        // group 0..7
    const int tg   = lane & 3;         // thread-in-group 0..3

    const int    n0 = blockIdx.x * GBN;          // n-tiles fastest -> X L2 reuse
    const size_t m0 = (size_t)blockIdx.y * GBM;

    // X staging: 2 threads per row; t-major row remap
    const int xrow = tid >> 1;          // 0..127
    const int xcol = (tid & 1) * 32;    // 0 or 32
    const int gm   = (int)m0 + xrow;    // t-major m index
    const float* Xp = X + ((size_t)(gm & 63) * TT + (gm >> 6)) * INN + xcol;

    // W cp.async: 2 threads per row, each 4x16B segments per plane
    const int wrow = tid >> 1;
    const int wseg = (tid & 1) * 4;
    const __half* Hp = g_Whi + (size_t)(n0 + wrow) * INN + wseg * 8;
    const __half* Lp = g_Wlo + (size_t)(n0 + wrow) * INN + wseg * 8;
    const uint32_t wdst = smb + (2 * PLANE_H + wrow * LDPH) * 2 + wseg * 16;

    float4 xa[8];
    auto gload = [&](int c) {
        const int k0 = c * GBK;
        #pragma unroll
        for (int i = 0; i < 8; i++)
            xa[i] = *(const float4*)(Xp + k0 + 4 * i);
    };
    auto wissue = [&](int c, int s) {
        const uint32_t d = wdst + s * STAGE_H * 2;
        const __half* hs = Hp + c * GBK;
        const __half* ls = Lp + c * GBK;
        #pragma unroll
        for (int i = 0; i < 4; i++) {
            cp_async16(d + i * 16,               hs + i * 8);
            cp_async16(d + PLANE_H * 2 + i * 16, ls + i * 8);
        }
    };
    auto sstore = [&](int s) {
        __half* Ah = smh + s * STAGE_H;
        __half* Al = Ah + PLANE_H;
        const int idx = xrow * LDPH + xcol;
        #pragma unroll
        for (int i = 0; i < 8; i++) {
            const float4 v = xa[i];
            const __half2 h0 = __floats2half2_rn(v.x, v.y);
            const __half2 h1 = __floats2half2_rn(v.z, v.w);
            const __half2 l0 = __floats2half2_rn(v.x - __low2float(h0),
                                                 v.y - __high2float(h0));
            const __half2 l1 = __floats2half2_rn(v.z - __low2float(h1),
                                                 v.w - __high2float(h1));
            *(__half2*)(Ah + idx + 4 * i)     = h0;
            *(__half2*)(Ah + idx + 4 * i + 2) = h1;
            *(__half2*)(Al + idx + 4 * i)     = l0;
            *(__half2*)(Al + idx + 4 * i + 2) = l1;
        }
    };

    float acc[4][4][4];
    #pragma unroll
    for (int i = 0; i < 4; i++)
        #pragma unroll
        for (int j = 0; j < 4; j++)
            #pragma unroll
            for (int q = 0; q < 4; q++) acc[i][j][q] = 0.0f;

    wissue(0, 0); cp_commit();
    gload(0);
    sstore(0);
    gload(1);
    cp_wait0();
    __syncthreads();

    for (int c = 0; c < NCHNK; c++) {
        const int cur = c & 1;
        if (c + 1 < NCHNK) {
            wissue(c + 1, 1 - cur);
            cp_commit();
            sstore(1 - cur);
        }
        if (c + 2 < NCHNK) gload(c + 2);

        const uint32_t* Ah32 = (const uint32_t*)(smh + cur * STAGE_H);
        const uint32_t* Al32 = Ah32 + PLANE_H / 2;
        const uint32_t* Bh32 = Ah32 + PLANE_H;
        const uint32_t* Bl32 = Ah32 + 3 * PLANE_H / 2;

        #pragma unroll
        for (int ks = 0; ks < 4; ks++) {
            const int kw = ks * 8 + tg;
            uint32_t ah[4][4], al[4][4], bh[4][2], bl[4][2];
            #pragma unroll
            for (int mb = 0; mb < 4; mb++) {
                const int r = (wm * 64 + mb * 16 + g) * (LDPH / 2) + kw;
                ah[mb][0] = Ah32[r];
                ah[mb][1] = Ah32[r + 8 * (LDPH / 2)];
                ah[mb][2] = Ah32[r + 4];
                ah[mb][3] = Ah32[r + 8 * (LDPH / 2) + 4];
                al[mb][0] = Al32[r];
                al[mb][1] = Al32[r + 8 * (LDPH / 2)];
                al[mb][2] = Al32[r + 4];
                al[mb][3] = Al32[r + 8 * (LDPH / 2) + 4];
            }
            #pragma unroll
            for (int nb = 0; nb < 4; nb++) {
                const int n = (wn * 32 + nb * 8 + g) * (LDPH / 2) + kw;
                bh[nb][0] = Bh32[n];
                bh[nb][1] = Bh32[n + 4];
                bl[nb][0] = Bl32[n];
                bl[nb][1] = Bl32[n + 4];
            }
            #pragma unroll
            for (int mb = 0; mb < 4; mb++)
                #pragma unroll
                for (int nb = 0; nb < 4; nb++)
                    MMA_F16(acc[mb][nb], ah[mb], bh[nb]);
            #pragma unroll
            for (int mb = 0; mb < 4; mb++)
                #pragma unroll
                for (int nb = 0; nb < 4; nb++)
                    MMA_F16(acc[mb][nb], ah[mb], bl[nb]);
            #pragma unroll
            for (int mb = 0; mb < 4; mb++)
                #pragma unroll
                for (int nb = 0; nb < 4; nb++)
                    MMA_F16(acc[mb][nb], al[mb], bh[nb]);
        }
        cp_wait0();
        __syncthreads();
    }

    // epilogue (t-major rows)
    #pragma unroll
    for (int mb = 0; mb < 4; mb++) {
        const size_t r = m0 + wm * 64 + mb * 16 + g;
        #pragma unroll
        for (int nb = 0; nb < 4; nb++) {
            const int col = n0 + wn * 32 + nb * 8 + tg * 2;
            *(float2*)(g_Wx + r * HH + col) =
                make_float2(acc[mb][nb][0], acc[mb][nb][1]);
            *(float2*)(g_Wx + (r + 8) * HH + col) =
                make_float2(acc[mb][nb][2], acc[mb][nb][3]);
        }
    }

    // publish tile progress: stores -> fence -> barrier -> elected release add
    __threadfence();
    __syncthreads();
    if (tid == 0) atomicAdd(&g_cnt[blockIdx.y], 1);
}

// ---------------------------------------------------------------------------
// Kernel 2: recurrent scan, 256 threads x 2 neurons (co-residency-sized).
//   Chases the GEMM wavefront: polls per-m-tile counters (ld.acquire) once
//   per 8-step block, before issuing that block's prefetch loads.
// ---------------------------------------------------------------------------
__global__ void __launch_bounds__(256, 1) scan_kernel(
    const float* __restrict__ alpha,
    const float* __restrict__ ut0,
    const float* __restrict__ st0,
    const float* __restrict__ V,
    float* __restrict__ out)
{
    const int b    = blockIdx.x;
    const int tid  = threadIdx.x;
    const int lane = tid & 31;
    const int wid  = tid >> 5;          // 0..7
    const int h0   = tid;
    const int h1   = tid + 256;

    __shared__ float    s_v[HH];
    __shared__ int      s_list[HH];
    __shared__ unsigned s_mask[16];

    const float a0 = fminf(fmaxf(alpha[h0], 0.81873075307798182f), 0.96078943915232320f);
    const float a1 = fminf(fmaxf(alpha[h1], 0.81873075307798182f), 0.96078943915232320f);
    const float oma0 = 1.0f - a0, oma1 = 1.0f - a1;
    const float vd0 = V[h0 * HH + h0];
    const float vd1 = V[h1 * HH + h1];

    float ut_0 = ut0[b * HH + h0], st_0 = st0[b * HH + h0];
    float ut_1 = ut0[b * HH + h1], st_1 = st0[b * HH + h1];

    s_v[h0] = st_0;
    s_v[h1] = st_1;
    __syncthreads();

    // Dense recurrent input for step 0 (continuous st0); remove diagonal.
    float rec0, rec1;
    {
        float p0 = 0.f, p1 = 0.f, p2 = 0.f, p3 = 0.f;
        float q0 = 0.f, q1 = 0.f, q2 = 0.f, q3 = 0.f;
        #pragma unroll 4
        for (int j = 0; j < HH; j += 4) {
            p0 = fmaf(s_v[j + 0], V[(j + 0) * HH + h0], p0);
            q0 = fmaf(s_v[j + 0], V[(j + 0) * HH + h1], q0);
            p1 = fmaf(s_v[j + 1], V[(j + 1) * HH + h0], p1);
            q1 = fmaf(s_v[j + 1], V[(j + 1) * HH + h1], q1);
            p2 = fmaf(s_v[j + 2], V[(j + 2) * HH + h0], p2);
            q2 = fmaf(s_v[j + 2], V[(j + 2) * HH + h1], q2);
            p3 = fmaf(s_v[j + 3], V[(j + 3) * HH + h0], p3);
            q3 = fmaf(s_v[j + 3], V[(j + 3) * HH + h1], q3);
        }
        rec0 = ((p0 + p1) + (p2 + p3)) - st_0 * vd0;
        rec1 = ((q0 + q1) + (q2 + q3)) - st_1 * vd1;
    }

    // t-major Wx: element (t, b, h) at g_Wx[(t*64+b)*512 + h]
    const float* wx0p = g_Wx + (size_t)b * HH + h0;
    const float* wx1p = g_Wx + (size_t)b * HH + h1;
    float* op0 = out + (size_t)b * TT * HH + h0;
    float* op1 = out + (size_t)b * TT * HH + h1;
    const size_t TSTRIDE = (size_t)64 * HH;

    int wmk = 0;   // tile watermark (thread 0 only)
    auto poll = [&](int need) {
        if (tid == 0) {
            while (wmk <= need) {
                int v;
                asm volatile("ld.acquire.gpu.global.b32 %0, [%1];"
                             : "=r"(v) : "l"(g_cnt + wmk) : "memory");
                if (v == 4) wmk++;
                else __nanosleep(256);
            }
        }
        __syncthreads();
    };

    // initial prefetch of t = 0..7 (tiles 0..3)
    poll(3);
    float wxb0[8], wxb1[8];
    #pragma unroll
    for (int i = 0; i < 8; i++) {
        wxb0[i] = __ldcs(wx0p + (size_t)i * TSTRIDE);
        wxb1[i] = __ldcs(wx1p + (size_t)i * TSTRIDE);
    }

    for (int t0 = 0; t0 < TT; t0 += 8) {
        // this block prefetches t0+8..t0+15 -> tiles up to t0/2+7
        int need = t0 / 2 + 7;
        poll(need < (MM / 128) ? need : (MM / 128) - 1);

        #pragma unroll
        for (int u = 0; u < 8; u++) {
            const int t = t0 + u;
            const float wx0 = wxb0[u];
            const float wx1 = wxb1[u];
            if (t + 8 < TT) {
                wxb0[u] = __ldcs(wx0p + (size_t)(t + 8) * TSTRIDE);
                wxb1[u] = __ldcs(wx1p + (size_t)(t + 8) * TSTRIDE);
            }

            ut_0 = a0 * (ut_0 - st_0) + oma0 * (wx0 + rec0);
            ut_1 = a1 * (ut_1 - st_1) + oma1 * (wx1 + rec1);
            const float sn0 = (ut_0 > 1.0f) ? 1.0f : 0.0f;
            const float sn1 = (ut_1 > 1.0f) ? 1.0f : 0.0f;
            __stcs(op0 + (size_t)t * HH, sn0);
            __stcs(op1 + (size_t)t * HH, sn1);

            const bool f0 = (sn0 != 0.0f);
            const bool f1 = (sn1 != 0.0f);
            const unsigned mlo = __ballot_sync(0xffffffffu, f0);
            const unsigned mhi = __ballot_sync(0xffffffffu, f1);
            if (lane == 0) { s_mask[wid] = mlo; s_mask[8 + wid] = mhi; }

            const int anyf = __syncthreads_count(f0 || f1);  // barrier A
            if (anyf == 0) { rec0 = 0.0f; rec1 = 0.0f; st_0 = sn0; st_1 = sn1; continue; }

            int off0 = 0, sum_lo = 0, off1 = 0, sum_hi = 0;
            #pragma unroll
            for (int w = 0; w < 8; w++) {
                const int p = __popc(s_mask[w]);
                if (w < wid) off0 += p;
                sum_lo += p;
            }
            #pragma unroll
            for (int w = 0; w < 8; w++) {
                const int p = __popc(s_mask[8 + w]);
                if (w < wid) off1 += p;
                sum_hi += p;
            }
            off1 += sum_lo;
            const int total = sum_lo + sum_hi;

            if (f0) s_list[off0 + __popc(mlo & ((1u << lane) - 1u))] = h0;
            if (f1) s_list[off1 + __popc(mhi & ((1u << lane) - 1u))] = h1;
            __syncthreads();                                 // barrier B

            float pa0 = 0.f, pa1 = 0.f, pa2 = 0.f, pa3 = 0.f;
            float qa0 = 0.f, qa1 = 0.f, qa2 = 0.f, qa3 = 0.f;
            int j = 0;
            for (; j + 4 <= total; j += 4) {
                const int i0 = s_list[j + 0], i1 = s_list[j + 1];
                const int i2 = s_list[j + 2], i3 = s_list[j + 3];
                pa0 += __ldg(V + i0 * HH + h0);
                qa0 += __ldg(V + i0 * HH + h1);
                pa1 += __ldg(V + i1 * HH + h0);
                qa1 += __ldg(V + i1 * HH + h1);
                pa2 += __ldg(V + i2 * HH + h0);
                qa2 += __ldg(V + i2 * HH + h1);
                pa3 += __ldg(V + i3 * HH + h0);
                qa3 += __ldg(V + i3 * HH + h1);
            }
            for (; j < total; j++) {
                const int i = s_list[j];
                pa0 += __ldg(V + i * HH + h0);
                qa0 += __ldg(V + i * HH + h1);
            }
            rec0 = ((pa0 + pa1) + (pa2 + pa3)) - (f0 ? vd0 : 0.0f);
            rec1 = ((qa0 + qa1) + (qa2 + qa3)) - (f1 ? vd1 : 0.0f);

            st_0 = sn0;
            st_1 = sn1;
        }
    }
}

// ---------------------------------------------------------------------------
// Launch: inputs: x, W, V, alpha, ut0, st0, input_layer
//   Two-stream fork/join (event edges are graph-capturable): GEMM on the
//   main stream, scan on a side stream chasing GEMM's per-tile counters.
// ---------------------------------------------------------------------------
extern "C" void kernel_launch(void* const* d_in, const int* in_sizes, int n_in,
                              void* d_out, int out_size) {
    const float* x     = (const float*)d_in[0];
    const float* W     = (const float*)d_in[1];
    const float* V     = (const float*)d_in[2];
    const float* alpha = (const float*)d_in[3];
    const float* ut0   = (const float*)d_in[4];
    const float* st0   = (const float*)d_in[5];
    float* out = (float*)d_out;

    static cudaStream_t s_scan = nullptr;
    static cudaEvent_t  ev_fork = nullptr, ev_join = nullptr;
    if (!s_scan) {
        cudaStreamCreateWithFlags(&s_scan, cudaStreamNonBlocking);
        cudaEventCreateWithFlags(&ev_fork, cudaEventDisableTiming);
        cudaEventCreateWithFlags(&ev_join, cudaEventDisableTiming);
    }

    cudaFuncSetAttribute(gemm2fp16_kernel,
                         cudaFuncAttributeMaxDynamicSharedMemorySize, GEMM_SMEM);

    prep_w_kernel<<<(HH * INN + 255) / 256, 256>>>(W);
    reset_cnt_kernel<<<1, 512>>>();

    cudaEventRecord(ev_fork, 0);
    cudaStreamWaitEvent(s_scan, ev_fork, 0);

    dim3 ggrid(HH / GBN, MM / GBM);   // 4 x 500 (n fastest; m-tiles ~in t order)
    gemm2fp16_kernel<<<ggrid, 256, GEMM_SMEM>>>(x);

    scan_kernel<<<BB, 256, 0, s_scan>>>(alpha, ut0, st0, V, out);

    cudaEventRecord(ev_join, s_scan);
    cudaStreamWaitEvent(0, ev_join, 0);
}

// round 10
// speedup vs baseline: 1.2801x; 1.2801x over previous
#include <cuda_runtime.h>
#include <cuda_fp16.h>
#include <cstdint>

// Problem dims (fixed by the dataset)
#define BB   64
#define TT   1000
#define INN  512
#define HH   512
#define MM   (BB * TT)   // 64000

#define NCHUNKS_T 5
#define TCH (TT / NCHUNKS_T)          // 200 steps per chunk
#define MTILES_CH (TCH * BB / 128)    // 100 m-tiles per chunk

// Scratch. g_Wx is T-MAJOR: row m = t*64 + b.
__device__ float  g_Wx[MM * HH];       // 131 MB  GEMM output (t-major)
__device__ __half g_Whi[HH * INN];     // 0.5 MB  fp16-hi of W
__device__ __half g_Wlo[HH * INN];     // 0.5 MB  fp16-lo of W
__device__ float  g_ut[BB * HH];       // scan state carry
__device__ float  g_st[BB * HH];
__device__ float  g_rec[BB * HH];

// cp.async helpers
__device__ __forceinline__ void cp_async16(uint32_t dst, const void* src) {
    asm volatile("cp.async.cg.shared.global [%0], [%1], 16;"
                 :: "r"(dst), "l"(src));
}
__device__ __forceinline__ uint32_t smem_u32(const void* p) {
    uint32_t a;
    asm("{ .reg .u64 t; cvta.to.shared.u64 t, %1; cvt.u32.u64 %0, t; }"
        : "=r"(a) : "l"(p));
    return a;
}
__device__ __forceinline__ void cp_commit() {
    asm volatile("cp.async.commit_group;" ::: "memory");
}
__device__ __forceinline__ void cp_wait0() {
    asm volatile("cp.async.wait_group 0;" ::: "memory");
}

// ---------------------------------------------------------------------------
// Kernel 0: W -> fp16 hi/lo split (once; tiny)
// ---------------------------------------------------------------------------
__global__ void prep_w_kernel(const float* __restrict__ W) {
    int i = blockIdx.x * blockDim.x + threadIdx.x;
    if (i < HH * INN) {
        float w   = W[i];
        __half hi = __float2half_rn(w);
        g_Whi[i]  = hi;
        g_Wlo[i]  = __float2half_rn(w - __half2float(hi));
    }
}

// ---------------------------------------------------------------------------
// Kernel 1: 2xFP16-split GEMM via mma.sync m16n8k16 (R8/R9 proven structure).
//   T-MAJOR output: Wx row m = t*64+b  ->  A row m reads X[b = m&63][t = m>>6].
//   ty0 = m-tile offset of this chunk.
// ---------------------------------------------------------------------------
#define GBM 128
#define GBN 128
#define GBK 64
#define LDPH 72
#define NCHNK (INN / GBK)             // 8
#define PLANE_H (GBM * LDPH)          // 9216 halfs per plane
#define STAGE_H (4 * PLANE_H)         // Ah | Al | Bh | Bl
#define GEMM_SMEM (2 * STAGE_H * 2)   // 147456 bytes

#define MMA_F16(d, a, b)                                                      \
    asm volatile(                                                             \
        "mma.sync.aligned.m16n8k16.row.col.f32.f16.f16.f32 "                  \
        "{%0,%1,%2,%3},{%4,%5,%6,%7},{%8,%9},{%0,%1,%2,%3};"                  \
        : "+f"((d)[0]), "+f"((d)[1]), "+f"((d)[2]), "+f"((d)[3])              \
        : "r"((a)[0]), "r"((a)[1]), "r"((a)[2]), "r"((a)[3]),                 \
          "r"((b)[0]), "r"((b)[1]))

__global__ void __launch_bounds__(256, 1) gemm2fp16_kernel(
    const float* __restrict__ X, int ty0)
{
    extern __shared__ __align__(16) __half smh[];
    const uint32_t smb = smem_u32(smh);

    const int tid  = threadIdx.x;
    const int lane = tid & 31;
    const int wm   = (tid >> 5) & 1;
    const int wn   = tid >> 6;
    const int g    = lane >> 2;
    const int tg   = lane & 3;

    const int    n0 = blockIdx.x * GBN;
    const size_t m0 = (size_t)(blockIdx.y + ty0) * GBM;

    // X staging: 2 threads per row; t-major row remap
    const int xrow = tid >> 1;
    const int xcol = (tid & 1) * 32;
    const int gm   = (int)m0 + xrow;
    const float* Xp = X + ((size_t)(gm & 63) * TT + (gm >> 6)) * INN + xcol;

    const int wrow = tid >> 1;
    const int wseg = (tid & 1) * 4;
    const __half* Hp = g_Whi + (size_t)(n0 + wrow) * INN + wseg * 8;
    const __half* Lp = g_Wlo + (size_t)(n0 + wrow) * INN + wseg * 8;
    const uint32_t wdst = smb + (2 * PLANE_H + wrow * LDPH) * 2 + wseg * 16;

    float4 xa[8];
    auto gload = [&](int c) {
        const int k0 = c * GBK;
        #pragma unroll
        for (int i = 0; i < 8; i++)
            xa[i] = *(const float4*)(Xp + k0 + 4 * i);
    };
    auto wissue = [&](int c, int s) {
        const uint32_t d = wdst + s * STAGE_H * 2;
        const __half* hs = Hp + c * GBK;
        const __half* ls = Lp + c * GBK;
        #pragma unroll
        for (int i = 0; i < 4; i++) {
            cp_async16(d + i * 16,               hs + i * 8);
            cp_async16(d + PLANE_H * 2 + i * 16, ls + i * 8);
        }
    };
    auto sstore = [&](int s) {
        __half* Ah = smh + s * STAGE_H;
        __half* Al = Ah + PLANE_H;
        const int idx = xrow * LDPH + xcol;
        #pragma unroll
        for (int i = 0; i < 8; i++) {
            const float4 v = xa[i];
            const __half2 h0 = __floats2half2_rn(v.x, v.y);
            const __half2 h1 = __floats2half2_rn(v.z, v.w);
            const __half2 l0 = __floats2half2_rn(v.x - __low2float(h0),
                                                 v.y - __high2float(h0));
            const __half2 l1 = __floats2half2_rn(v.z - __low2float(h1),
                                                 v.w - __high2float(h1));
            *(__half2*)(Ah + idx + 4 * i)     = h0;
            *(__half2*)(Ah + idx + 4 * i + 2) = h1;
            *(__half2*)(Al + idx + 4 * i)     = l0;
            *(__half2*)(Al + idx + 4 * i + 2) = l1;
        }
    };

    float acc[4][4][4];
    #pragma unroll
    for (int i = 0; i < 4; i++)
        #pragma unroll
        for (int j = 0; j < 4; j++)
            #pragma unroll
            for (int q = 0; q < 4; q++) acc[i][j][q] = 0.0f;

    wissue(0, 0); cp_commit();
    gload(0);
    sstore(0);
    gload(1);
    cp_wait0();
    __syncthreads();

    for (int c = 0; c < NCHNK; c++) {
        const int cur = c & 1;
        if (c + 1 < NCHNK) {
            wissue(c + 1, 1 - cur);
            cp_commit();
            sstore(1 - cur);
        }
        if (c + 2 < NCHNK) gload(c + 2);

        const uint32_t* Ah32 = (const uint32_t*)(smh + cur * STAGE_H);
        const uint32_t* Al32 = Ah32 + PLANE_H / 2;
        const uint32_t* Bh32 = Ah32 + PLANE_H;
        const uint32_t* Bl32 = Ah32 + 3 * PLANE_H / 2;

        #pragma unroll
        for (int ks = 0; ks < 4; ks++) {
            const int kw = ks * 8 + tg;
            uint32_t ah[4][4], al[4][4], bh[4][2], bl[4][2];
            #pragma unroll
            for (int mb = 0; mb < 4; mb++) {
                const int r = (wm * 64 + mb * 16 + g) * (LDPH / 2) + kw;
                ah[mb][0] = Ah32[r];
                ah[mb][1] = Ah32[r + 8 * (LDPH / 2)];
                ah[mb][2] = Ah32[r + 4];
                ah[mb][3] = Ah32[r + 8 * (LDPH / 2) + 4];
                al[mb][0] = Al32[r];
                al[mb][1] = Al32[r + 8 * (LDPH / 2)];
                al[mb][2] = Al32[r + 4];
                al[mb][3] = Al32[r + 8 * (LDPH / 2) + 4];
            }
            #pragma unroll
            for (int nb = 0; nb < 4; nb++) {
                const int n = (wn * 32 + nb * 8 + g) * (LDPH / 2) + kw;
                bh[nb][0] = Bh32[n];
                bh[nb][1] = Bh32[n + 4];
                bl[nb][0] = Bl32[n];
                bl[nb][1] = Bl32[n + 4];
            }
            #pragma unroll
            for (int mb = 0; mb < 4; mb++)
                #pragma unroll
                for (int nb = 0; nb < 4; nb++)
                    MMA_F16(acc[mb][nb], ah[mb], bh[nb]);
            #pragma unroll
            for (int mb = 0; mb < 4; mb++)
                #pragma unroll
                for (int nb = 0; nb < 4; nb++)
                    MMA_F16(acc[mb][nb], ah[mb], bl[nb]);
            #pragma unroll
            for (int mb = 0; mb < 4; mb++)
                #pragma unroll
                for (int nb = 0; nb < 4; nb++)
                    MMA_F16(acc[mb][nb], al[mb], bh[nb]);
        }
        cp_wait0();
        __syncthreads();
    }

    #pragma unroll
    for (int mb = 0; mb < 4; mb++) {
        const size_t r = m0 + wm * 64 + mb * 16 + g;
        #pragma unroll
        for (int nb = 0; nb < 4; nb++) {
            const int col = n0 + wn * 32 + nb * 8 + tg * 2;
            *(float2*)(g_Wx + r * HH + col) =
                make_float2(acc[mb][nb][0], acc[mb][nb][1]);
            *(float2*)(g_Wx + (r + 8) * HH + col) =
                make_float2(acc[mb][nb][2], acc[mb][nb][3]);
        }
    }
}

// ---------------------------------------------------------------------------
// Kernel 2: recurrent scan chunk [t0, t1). R8's proven 512-thread internals;
//   ut/st/rec carried across chunks via __device__ globals.
// ---------------------------------------------------------------------------
__global__ void __launch_bounds__(512, 1) scan_kernel(
    const float* __restrict__ alpha,
    const float* __restrict__ ut0,
    const float* __restrict__ st0,
    const float* __restrict__ V,
    float* __restrict__ out,
    int t0, int t1, int first)
{
    const int b    = blockIdx.x;
    const int h    = threadIdx.x;
    const int lane = h & 31;
    const int wid  = h >> 5;

    __shared__ float    s_v[HH];
    __shared__ int      s_list[HH];
    __shared__ unsigned s_mask[16];

    const float a   = fminf(fmaxf(alpha[h], 0.81873075307798182f), 0.96078943915232320f);
    const float oma = 1.0f - a;
    const float vdiag = V[h * HH + h];

    float ut, st_prev, rec;
    if (first) {
        ut      = ut0[b * HH + h];
        st_prev = st0[b * HH + h];
        s_v[h] = st_prev;
        __syncthreads();
        float r0 = 0.f, r1 = 0.f, r2 = 0.f, r3 = 0.f;
        #pragma unroll 4
        for (int j = 0; j < HH; j += 4) {
            r0 = fmaf(s_v[j + 0], V[(j + 0) * HH + h], r0);
            r1 = fmaf(s_v[j + 1], V[(j + 1) * HH + h], r1);
            r2 = fmaf(s_v[j + 2], V[(j + 2) * HH + h], r2);
            r3 = fmaf(s_v[j + 3], V[(j + 3) * HH + h], r3);
        }
        rec = ((r0 + r1) + (r2 + r3)) - st_prev * vdiag;
    } else {
        ut      = g_ut [b * HH + h];
        st_prev = g_st [b * HH + h];
        rec     = g_rec[b * HH + h];
    }

    // t-major Wx: element (t, b, h) at g_Wx[(t*64+b)*512 + h]
    const size_t TSTRIDE = (size_t)64 * HH;
    const float* wxp = g_Wx + (size_t)b * HH + h;
    float*       op  = out  + (size_t)b * TT * HH + h;

    float wxb[8];
    #pragma unroll
    for (int i = 0; i < 8; i++) wxb[i] = __ldcs(wxp + (size_t)(t0 + i) * TSTRIDE);

    for (int tb = t0; tb < t1; tb += 8) {
        #pragma unroll
        for (int u = 0; u < 8; u++) {
            const int t = tb + u;
            const float wx = wxb[u];
            if (t + 8 < t1) wxb[u] = __ldcs(wxp + (size_t)(t + 8) * TSTRIDE);

            ut = a * (ut - st_prev) + oma * (wx + rec);
            const float st_new = (ut > 1.0f) ? 1.0f : 0.0f;
            __stcs(op + (size_t)t * HH, st_new);

            const bool fired = (st_new != 0.0f);
            const unsigned m = __ballot_sync(0xffffffffu, fired);
            if (lane == 0) s_mask[wid] = m;

            const int nf = __syncthreads_count(fired);   // barrier A
            if (nf == 0) { rec = 0.0f; st_prev = st_new; continue; }

            int off = 0;
            #pragma unroll
            for (int w = 0; w < 16; w++)
                off += (w < wid) ? __popc(s_mask[w]) : 0;
            if (fired)
                s_list[off + __popc(m & ((1u << lane) - 1u))] = h;
            __syncthreads();                              // barrier B

            float rr0 = 0.f, rr1 = 0.f, rr2 = 0.f, rr3 = 0.f;
            float rr4 = 0.f, rr5 = 0.f, rr6 = 0.f, rr7 = 0.f;
            int j = 0;
            for (; j + 8 <= nf; j += 8) {
                const int i0 = s_list[j + 0], i1 = s_list[j + 1];
                const int i2 = s_list[j + 2], i3 = s_list[j + 3];
                const int i4 = s_list[j + 4], i5 = s_list[j + 5];
                const int i6 = s_list[j + 6], i7 = s_list[j + 7];
                rr0 += __ldg(V + i0 * HH + h);
                rr1 += __ldg(V + i1 * HH + h);
                rr2 += __ldg(V + i2 * HH + h);
                rr3 += __ldg(V + i3 * HH + h);
                rr4 += __ldg(V + i4 * HH + h);
                rr5 += __ldg(V + i5 * HH + h);
                rr6 += __ldg(V + i6 * HH + h);
                rr7 += __ldg(V + i7 * HH + h);
            }
            for (; j < nf; j++) rr0 += __ldg(V + s_list[j] * HH + h);

            rec = (((rr0 + rr1) + (rr2 + rr3)) + ((rr4 + rr5) + (rr6 + rr7)))
                  - (fired ? vdiag : 0.0f);

            st_prev = st_new;
        }
    }

    // carry state to next chunk
    g_ut [b * HH + h] = ut;
    g_st [b * HH + h] = st_prev;
    g_rec[b * HH + h] = rec;
}

// ---------------------------------------------------------------------------
// Launch: inputs: x, W, V, alpha, ut0, st0, input_layer
//   5 GEMM chunks alternate across two streams (no drain bubbles between
//   chunks); scan chunk k event-gated on gemm chunk k, on a HIGH-PRIORITY
//   stream so freed SMs take scan CTAs first.
// ---------------------------------------------------------------------------
extern "C" void kernel_launch(void* const* d_in, const int* in_sizes, int n_in,
                              void* d_out, int out_size) {
    const float* x     = (const float*)d_in[0];
    const float* W     = (const float*)d_in[1];
    const float* V     = (const float*)d_in[2];
    const float* alpha = (const float*)d_in[3];
    const float* ut0   = (const float*)d_in[4];
    const float* st0   = (const float*)d_in[5];
    float* out = (float*)d_out;

    static cudaStream_t sA = nullptr, sB = nullptr, sScan = nullptr;
    static cudaEvent_t  evPrep = nullptr, evG[NCHUNKS_T], evJoin = nullptr;
    if (!sA) {
        int lo, hi;
        cudaDeviceGetStreamPriorityRange(&lo, &hi);   // hi = greatest priority
        cudaStreamCreateWithFlags(&sA, cudaStreamNonBlocking);
        cudaStreamCreateWithFlags(&sB, cudaStreamNonBlocking);
        cudaStreamCreateWithPriority(&sScan, cudaStreamNonBlocking, hi);
        cudaEventCreateWithFlags(&evPrep, cudaEventDisableTiming);
        for (int k = 0; k < NCHUNKS_T; k++)
            cudaEventCreateWithFlags(&evG[k], cudaEventDisableTiming);
        cudaEventCreateWithFlags(&evJoin, cudaEventDisableTiming);
    }

    cudaFuncSetAttribute(gemm2fp16_kernel,
                         cudaFuncAttributeMaxDynamicSharedMemorySize, GEMM_SMEM);

    prep_w_kernel<<<(HH * INN + 255) / 256, 256>>>(W);
    cudaEventRecord(evPrep, 0);
    cudaStreamWaitEvent(sA, evPrep, 0);
    cudaStreamWaitEvent(sB, evPrep, 0);

    for (int k = 0; k < NCHUNKS_T; k++) {
        cudaStream_t sg = (k & 1) ? sB : sA;
        dim3 ggrid(HH / GBN, MTILES_CH);   // 4 x 100
        gemm2fp16_kernel<<<ggrid, 256, GEMM_SMEM, sg>>>(x, k * MTILES_CH);
        cudaEventRecord(evG[k], sg);

        cudaStreamWaitEvent(sScan, evG[k], 0);
        scan_kernel<<<BB, HH, 0, sScan>>>(alpha, ut0, st0, V, out,
                                          k * TCH, (k + 1) * TCH, k == 0);
    }

    cudaEventRecord(evJoin, sScan);
    cudaStreamWaitEvent(0, evJoin, 0);
}

// round 11
// speedup vs baseline: 1.6417x; 1.2825x over previous
#include <cuda_runtime.h>
#include <cuda_fp16.h>
#include <cstdint>

// Problem dims (fixed by the dataset)
#define BB   64
#define TT   1000
#define INN  512
#define HH   512
#define MM   (BB * TT)   // 64000

#define NCHUNKS_T 5
#define TCH (TT / NCHUNKS_T)          // 200 steps per chunk
#define MTILES_CH (TCH * BB / 128)    // 100 m-tiles per chunk

// Scratch. g_Wx is T-MAJOR: row m = t*64 + b.
__device__ float  g_Wx[MM * HH];       // 131 MB  GEMM output (t-major)
__device__ __half g_Whi[HH * INN];     // 0.5 MB  fp16-hi of W
__device__ __half g_Wlo[HH * INN];     // 0.5 MB  fp16-lo of W
__device__ float  g_ut[BB * HH];       // scan state carry
__device__ float  g_st[BB * HH];
__device__ float  g_rec[BB * HH];

// cp.async helpers
__device__ __forceinline__ void cp_async16(uint32_t dst, const void* src) {
    asm volatile("cp.async.cg.shared.global [%0], [%1], 16;"
                 :: "r"(dst), "l"(src));
}
__device__ __forceinline__ uint32_t smem_u32(const void* p) {
    uint32_t a;
    asm("{ .reg .u64 t; cvta.to.shared.u64 t, %1; cvt.u32.u64 %0, t; }"
        : "=r"(a) : "l"(p));
    return a;
}
__device__ __forceinline__ void cp_commit() {
    asm volatile("cp.async.commit_group;" ::: "memory");
}
__device__ __forceinline__ void cp_wait0() {
    asm volatile("cp.async.wait_group 0;" ::: "memory");
}

// ---------------------------------------------------------------------------
// Kernel 0: W -> fp16 hi/lo split (once; tiny)
// ---------------------------------------------------------------------------
__global__ void prep_w_kernel(const float* __restrict__ W) {
    int i = blockIdx.x * blockDim.x + threadIdx.x;
    if (i < HH * INN) {
        float w   = W[i];
        __half hi = __float2half_rn(w);
        g_Whi[i]  = hi;
        g_Wlo[i]  = __float2half_rn(w - __half2float(hi));
    }
}

// ---------------------------------------------------------------------------
// Kernel 1: 2xFP16-split GEMM via mma.sync m16n8k16.
//   GBK=32 / smem 2x40KB -> TWO CTAs per SM (4 warps/SMSP) so the fragment-
//   LDS crossbar phase of one CTA overlaps the MMA phase of the other.
//   Same fragment values + per-acc accumulation order as R10 (bit-identical).
// ---------------------------------------------------------------------------
#define GBM 128
#define GBN 128
#define GBK 32
#define LDPH 40                       // halfs/row; (20g+tg)%32 conflict-free
#define NCHNK (INN / GBK)             // 16
#define PLANE_H (GBM * LDPH)          // 5120 halfs per plane
#define STAGE_H (4 * PLANE_H)         // Ah | Al | Bh | Bl
#define GEMM_SMEM (2 * STAGE_H * 2)   // 81920 bytes

#define MMA_F16(d, a, b)                                                      \
    asm volatile(                                                             \
        "mma.sync.aligned.m16n8k16.row.col.f32.f16.f16.f32 "                  \
        "{%0,%1,%2,%3},{%4,%5,%6,%7},{%8,%9},{%0,%1,%2,%3};"                  \
        : "+f"((d)[0]), "+f"((d)[1]), "+f"((d)[2]), "+f"((d)[3])              \
        : "r"((a)[0]), "r"((a)[1]), "r"((a)[2]), "r"((a)[3]),                 \
          "r"((b)[0]), "r"((b)[1]))

__global__ void __launch_bounds__(256, 2) gemm2fp16_kernel(
    const float* __restrict__ X, int ty0)
{
    extern __shared__ __align__(16) __half smh[];
    const uint32_t smb = smem_u32(smh);

    const int tid  = threadIdx.x;
    const int lane = tid & 31;
    const int wm   = (tid >> 5) & 1;
    const int wn   = tid >> 6;
    const int g    = lane >> 2;
    const int tg   = lane & 3;

    const int    n0 = blockIdx.x * GBN;
    const size_t m0 = (size_t)(blockIdx.y + ty0) * GBM;

    // X staging: 2 threads per row, 16 consecutive floats each (4 float4)
    const int xrow = tid >> 1;
    const int xcol = (tid & 1) * 16;
    const int gm   = (int)m0 + xrow;
    const float* Xp = X + ((size_t)(gm & 63) * TT + (gm >> 6)) * INN + xcol;

    // W cp.async: per plane 128 rows x 64B = 512 x 16B segs; 2 per thread
    const int wrow0 = tid >> 1;              // segs tid*? -> use s = tid, tid+256
    const uint32_t bh_base = smb + (2 * PLANE_H) * 2;   // bytes
    const uint32_t bl_base = smb + (3 * PLANE_H) * 2;

    float4 xa[4];
    auto gload = [&](int c) {
        const int k0 = c * GBK;
        #pragma unroll
        for (int i = 0; i < 4; i++)
            xa[i] = *(const float4*)(Xp + k0 + 4 * i);
    };
    auto wissue = [&](int c, int s) {
        const uint32_t soff = (uint32_t)s * STAGE_H * 2;
        #pragma unroll
        for (int i = 0; i < 2; i++) {
            const int sid = tid + i * 256;    // 0..511
            const int row = sid >> 2;
            const int seg = sid & 3;
            const uint32_t d = soff + (uint32_t)(row * LDPH * 2 + seg * 16);
            cp_async16(bh_base + d, g_Whi + (size_t)(n0 + row) * INN + c * GBK + seg * 8);
            cp_async16(bl_base + d, g_Wlo + (size_t)(n0 + row) * INN + c * GBK + seg * 8);
        }
    };
    auto sstore = [&](int s) {
        __half* Ah = smh + s * STAGE_H;
        __half* Al = Ah + PLANE_H;
        const int idx = xrow * LDPH + xcol;
        #pragma unroll
        for (int i = 0; i < 4; i++) {
            const float4 v = xa[i];
            const __half2 h0 = __floats2half2_rn(v.x, v.y);
            const __half2 h1 = __floats2half2_rn(v.z, v.w);
            const __half2 l0 = __floats2half2_rn(v.x - __low2float(h0),
                                                 v.y - __high2float(h0));
            const __half2 l1 = __floats2half2_rn(v.z - __low2float(h1),
                                                 v.w - __high2float(h1));
            *(__half2*)(Ah + idx + 4 * i)     = h0;
            *(__half2*)(Ah + idx + 4 * i + 2) = h1;
            *(__half2*)(Al + idx + 4 * i)     = l0;
            *(__half2*)(Al + idx + 4 * i + 2) = l1;
        }
    };

    float acc[4][4][4];
    #pragma unroll
    for (int i = 0; i < 4; i++)
        #pragma unroll
        for (int j = 0; j < 4; j++)
            #pragma unroll
            for (int q = 0; q < 4; q++) acc[i][j][q] = 0.0f;

    wissue(0, 0); cp_commit();
    gload(0);
    sstore(0);
    gload(1);
    cp_wait0();
    __syncthreads();

    for (int c = 0; c < NCHNK; c++) {
        const int cur = c & 1;
        if (c + 1 < NCHNK) {
            wissue(c + 1, 1 - cur);
            cp_commit();
            sstore(1 - cur);
        }
        if (c + 2 < NCHNK) gload(c + 2);

        const uint32_t* Ah32 = (const uint32_t*)(smh + cur * STAGE_H);
        const uint32_t* Al32 = Ah32 + PLANE_H / 2;
        const uint32_t* Bh32 = Ah32 + PLANE_H;
        const uint32_t* Bl32 = Ah32 + 3 * PLANE_H / 2;

        #pragma unroll
        for (int ks = 0; ks < 2; ks++) {
            const int kw = ks * 8 + tg;
            uint32_t ah[4][4], al[4][4], bh[4][2], bl[4][2];
            #pragma unroll
            for (int mb = 0; mb < 4; mb++) {
                const int r = (wm * 64 + mb * 16 + g) * (LDPH / 2) + kw;
                ah[mb][0] = Ah32[r];
                ah[mb][1] = Ah32[r + 8 * (LDPH / 2)];
                ah[mb][2] = Ah32[r + 4];
                ah[mb][3] = Ah32[r + 8 * (LDPH / 2) + 4];
                al[mb][0] = Al32[r];
                al[mb][1] = Al32[r + 8 * (LDPH / 2)];
                al[mb][2] = Al32[r + 4];
                al[mb][3] = Al32[r + 8 * (LDPH / 2) + 4];
            }
            #pragma unroll
            for (int nb = 0; nb < 4; nb++) {
                const int n = (wn * 32 + nb * 8 + g) * (LDPH / 2) + kw;
                bh[nb][0] = Bh32[n];
                bh[nb][1] = Bh32[n + 4];
                bl[nb][0] = Bl32[n];
                bl[nb][1] = Bl32[n + 4];
            }
            #pragma unroll
            for (int mb = 0; mb < 4; mb++)
                #pragma unroll
                for (int nb = 0; nb < 4; nb++)
                    MMA_F16(acc[mb][nb], ah[mb], bh[nb]);
            #pragma unroll
            for (int mb = 0; mb < 4; mb++)
                #pragma unroll
                for (int nb = 0; nb < 4; nb++)
                    MMA_F16(acc[mb][nb], ah[mb], bl[nb]);
            #pragma unroll
            for (int mb = 0; mb < 4; mb++)
                #pragma unroll
                for (int nb = 0; nb < 4; nb++)
                    MMA_F16(acc[mb][nb], al[mb], bh[nb]);
        }
        cp_wait0();
        __syncthreads();
    }

    #pragma unroll
    for (int mb = 0; mb < 4; mb++) {
        const size_t r = m0 + wm * 64 + mb * 16 + g;
        #pragma unroll
        for (int nb = 0; nb < 4; nb++) {
            const int col = n0 + wn * 32 + nb * 8 + tg * 2;
            *(float2*)(g_Wx + r * HH + col) =
                make_float2(acc[mb][nb][0], acc[mb][nb][1]);
            *(float2*)(g_Wx + (r + 8) * HH + col) =
                make_float2(acc[mb][nb][2], acc[mb][nb][3]);
        }
    }
}

// ---------------------------------------------------------------------------
// Kernel 2: recurrent scan chunk [t0, t1). R8's proven 512-thread internals;
//   ut/st/rec carried across chunks via __device__ globals.
// ---------------------------------------------------------------------------
__global__ void __launch_bounds__(512, 1) scan_kernel(
    const float* __restrict__ alpha,
    const float* __restrict__ ut0,
    const float* __restrict__ st0,
    const float* __restrict__ V,
    float* __restrict__ out,
    int t0, int t1, int first)
{
    const int b    = blockIdx.x;
    const int h    = threadIdx.x;
    const int lane = h & 31;
    const int wid  = h >> 5;

    __shared__ float    s_v[HH];
    __shared__ int      s_list[HH];
    __shared__ unsigned s_mask[16];

    const float a   = fminf(fmaxf(alpha[h], 0.81873075307798182f), 0.96078943915232320f);
    const float oma = 1.0f - a;
    const float vdiag = V[h * HH + h];

    float ut, st_prev, rec;
    if (first) {
        ut      = ut0[b * HH + h];
        st_prev = st0[b * HH + h];
        s_v[h] = st_prev;
        __syncthreads();
        float r0 = 0.f, r1 = 0.f, r2 = 0.f, r3 = 0.f;
        #pragma unroll 4
        for (int j = 0; j < HH; j += 4) {
            r0 = fmaf(s_v[j + 0], V[(j + 0) * HH + h], r0);
            r1 = fmaf(s_v[j + 1], V[(j + 1) * HH + h], r1);
            r2 = fmaf(s_v[j + 2], V[(j + 2) * HH + h], r2);
            r3 = fmaf(s_v[j + 3], V[(j + 3) * HH + h], r3);
        }
        rec = ((r0 + r1) + (r2 + r3)) - st_prev * vdiag;
    } else {
        ut      = g_ut [b * HH + h];
        st_prev = g_st [b * HH + h];
        rec     = g_rec[b * HH + h];
    }

    // t-major Wx: element (t, b, h) at g_Wx[(t*64+b)*512 + h]
    const size_t TSTRIDE = (size_t)64 * HH;
    const float* wxp = g_Wx + (size_t)b * HH + h;
    float*       op  = out  + (size_t)b * TT * HH + h;

    float wxb[8];
    #pragma unroll
    for (int i = 0; i < 8; i++) wxb[i] = __ldcs(wxp + (size_t)(t0 + i) * TSTRIDE);

    for (int tb = t0; tb < t1; tb += 8) {
        #pragma unroll
        for (int u = 0; u < 8; u++) {
            const int t = tb + u;
            const float wx = wxb[u];
            if (t + 8 < t1) wxb[u] = __ldcs(wxp + (size_t)(t + 8) * TSTRIDE);

            ut = a * (ut - st_prev) + oma * (wx + rec);
            const float st_new = (ut > 1.0f) ? 1.0f : 0.0f;
            __stcs(op + (size_t)t * HH, st_new);

            const bool fired = (st_new != 0.0f);
            const unsigned m = __ballot_sync(0xffffffffu, fired);
            if (lane == 0) s_mask[wid] = m;

            const int nf = __syncthreads_count(fired);   // barrier A
            if (nf == 0) { rec = 0.0f; st_prev = st_new; continue; }

            int off = 0;
            #pragma unroll
            for (int w = 0; w < 16; w++)
                off += (w < wid) ? __popc(s_mask[w]) : 0;
            if (fired)
                s_list[off + __popc(m & ((1u << lane) - 1u))] = h;
            __syncthreads();                              // barrier B

            float rr0 = 0.f, rr1 = 0.f, rr2 = 0.f, rr3 = 0.f;
            float rr4 = 0.f, rr5 = 0.f, rr6 = 0.f, rr7 = 0.f;
            int j = 0;
            for (; j + 8 <= nf; j += 8) {
                const int i0 = s_list[j + 0], i1 = s_list[j + 1];
                const int i2 = s_list[j + 2], i3 = s_list[j + 3];
                const int i4 = s_list[j + 4], i5 = s_list[j + 5];
                const int i6 = s_list[j + 6], i7 = s_list[j + 7];
                rr0 += __ldg(V + i0 * HH + h);
                rr1 += __ldg(V + i1 * HH + h);
                rr2 += __ldg(V + i2 * HH + h);
                rr3 += __ldg(V + i3 * HH + h);
                rr4 += __ldg(V + i4 * HH + h);
                rr5 += __ldg(V + i5 * HH + h);
                rr6 += __ldg(V + i6 * HH + h);
                rr7 += __ldg(V + i7 * HH + h);
            }
            for (; j < nf; j++) rr0 += __ldg(V + s_list[j] * HH + h);

            rec = (((rr0 + rr1) + (rr2 + rr3)) + ((rr4 + rr5) + (rr6 + rr7)))
                  - (fired ? vdiag : 0.0f);

            st_prev = st_new;
        }
    }

    // carry state to next chunk
    g_ut [b * HH + h] = ut;
    g_st [b * HH + h] = st_prev;
    g_rec[b * HH + h] = rec;
}

// ---------------------------------------------------------------------------
// Launch: inputs: x, W, V, alpha, ut0, st0, input_layer
//   5 GEMM chunks alternate across two streams; scan chunk k event-gated on
//   gemm chunk k, on a HIGH-PRIORITY stream.
// ---------------------------------------------------------------------------
extern "C" void kernel_launch(void* const* d_in, const int* in_sizes, int n_in,
                              void* d_out, int out_size) {
    const float* x     = (const float*)d_in[0];
    const float* W     = (const float*)d_in[1];
    const float* V     = (const float*)d_in[2];
    const float* alpha = (const float*)d_in[3];
    const float* ut0   = (const float*)d_in[4];
    const float* st0   = (const float*)d_in[5];
    float* out = (float*)d_out;

    static cudaStream_t sA = nullptr, sB = nullptr, sScan = nullptr;
    static cudaEvent_t  evPrep = nullptr, evG[NCHUNKS_T], evJoin = nullptr;
    if (!sA) {
        int lo, hi;
        cudaDeviceGetStreamPriorityRange(&lo, &hi);
        cudaStreamCreateWithFlags(&sA, cudaStreamNonBlocking);
        cudaStreamCreateWithFlags(&sB, cudaStreamNonBlocking);
        cudaStreamCreateWithPriority(&sScan, cudaStreamNonBlocking, hi);
        cudaEventCreateWithFlags(&evPrep, cudaEventDisableTiming);
        for (int k = 0; k < NCHUNKS_T; k++)
            cudaEventCreateWithFlags(&evG[k], cudaEventDisableTiming);
        cudaEventCreateWithFlags(&evJoin, cudaEventDisableTiming);
    }

    cudaFuncSetAttribute(gemm2fp16_kernel,
                         cudaFuncAttributeMaxDynamicSharedMemorySize, GEMM_SMEM);

    prep_w_kernel<<<(HH * INN + 255) / 256, 256>>>(W);
    cudaEventRecord(evPrep, 0);
    cudaStreamWaitEvent(sA, evPrep, 0);
    cudaStreamWaitEvent(sB, evPrep, 0);

    for (int k = 0; k < NCHUNKS_T; k++) {
        cudaStream_t sg = (k & 1) ? sB : sA;
        dim3 ggrid(HH / GBN, MTILES_CH);   // 4 x 100
        gemm2fp16_kernel<<<ggrid, 256, GEMM_SMEM, sg>>>(x, k * MTILES_CH);
        cudaEventRecord(evG[k], sg);

        cudaStreamWaitEvent(sScan, evG[k], 0);
        scan_kernel<<<BB, HH, 0, sScan>>>(alpha, ut0, st0, V, out,
                                          k * TCH, (k + 1) * TCH, k == 0);
    }

    cudaEventRecord(evJoin, sScan);
    cudaStreamWaitEvent(0, evJoin, 0);
}

// round 12
// speedup vs baseline: 1.7478x; 1.0646x over previous
#include <cuda_runtime.h>
#include <cuda_fp16.h>
#include <cstdint>

// Problem dims (fixed by the dataset)
#define BB   64
#define TT   1000
#define INN  512
#define HH   512
#define MM   (BB * TT)   // 64000

#define NCHUNKS_T 5

// Scratch. g_Wx is T-MAJOR: row m = t*64 + b.
__device__ float  g_Wx[MM * HH];       // 131 MB  GEMM output (t-major)
__device__ __half g_Whi[HH * INN];     // 0.5 MB  fp16-hi of W
__device__ __half g_Wlo[HH * INN];     // 0.5 MB  fp16-lo of W
__device__ float  g_ut[BB * HH];       // scan state carry
__device__ float  g_st[BB * HH];
__device__ float  g_rec[BB * HH];

// helpers
__device__ __forceinline__ void cp_async16(uint32_t dst, const void* src) {
    asm volatile("cp.async.cg.shared.global [%0], [%1], 16;"
                 :: "r"(dst), "l"(src));
}
__device__ __forceinline__ uint32_t smem_u32(const void* p) {
    uint32_t a;
    asm("{ .reg .u64 t; cvta.to.shared.u64 t, %1; cvt.u32.u64 %0, t; }"
        : "=r"(a) : "l"(p));
    return a;
}
__device__ __forceinline__ void cp_commit() {
    asm volatile("cp.async.commit_group;" ::: "memory");
}
__device__ __forceinline__ void cp_wait0() {
    asm volatile("cp.async.wait_group 0;" ::: "memory");
}

// ---------------------------------------------------------------------------
// Kernel 0: W -> fp16 hi/lo split (once; tiny)
// ---------------------------------------------------------------------------
__global__ void prep_w_kernel(const float* __restrict__ W) {
    int i = blockIdx.x * blockDim.x + threadIdx.x;
    if (i < HH * INN) {
        float w   = W[i];
        __half hi = __float2half_rn(w);
        g_Whi[i]  = hi;
        g_Wlo[i]  = __float2half_rn(w - __half2float(hi));
    }
}

// ---------------------------------------------------------------------------
// Kernel 1: 2xFP16-split GEMM via mma.sync m16n8k16, 2 CTAs/SM.
//   ldmatrix fragment loads (48 scalar LDS -> 8 ldmatrix.x4 per k-step) with
//   phased limb residency (hh -> hl -> lh) to cut register pressure.
//   Fragment values + per-acc accumulation order bit-identical to R11.
// ---------------------------------------------------------------------------
#define GBM 128
#define GBN 128
#define GBK 32
#define LDPH 40                       // halfs/row; conflict-free rows
#define NCHNK (INN / GBK)             // 16
#define PLANE_H (GBM * LDPH)          // 5120 halfs per plane
#define STAGE_H (4 * PLANE_H)         // Ah | Al | Bh | Bl
#define GEMM_SMEM (2 * STAGE_H * 2)   // 81920 bytes

#define MMA_F16(d, a, b)                                                      \
    asm volatile(                                                             \
        "mma.sync.aligned.m16n8k16.row.col.f32.f16.f16.f32 "                  \
        "{%0,%1,%2,%3},{%4,%5,%6,%7},{%8,%9},{%0,%1,%2,%3};"                  \
        : "+f"((d)[0]), "+f"((d)[1]), "+f"((d)[2]), "+f"((d)[3])              \
        : "r"((a)[0]), "r"((a)[1]), "r"((a)[2]), "r"((a)[3]),                 \
          "r"((b)[0]), "r"((b)[1]))

#define LDSM_X4(r0, r1, r2, r3, addr)                                        \
    asm volatile(                                                             \
        "ldmatrix.sync.aligned.m8n8.x4.shared.b16 {%0,%1,%2,%3}, [%4];"       \
        : "=r"(r0), "=r"(r1), "=r"(r2), "=r"(r3) : "r"(addr))

__global__ void __launch_bounds__(256, 2) gemm2fp16_kernel(
    const float* __restrict__ X, int ty0)
{
    extern __shared__ __align__(16) __half smh[];
    const uint32_t smb = smem_u32(smh);

    const int tid  = threadIdx.x;
    const int lane = tid & 31;
    const int wm   = (tid >> 5) & 1;
    const int wn   = tid >> 6;
    const int g    = lane >> 2;
    const int tg   = lane & 3;

    const int    n0 = blockIdx.x * GBN;
    const size_t m0 = (size_t)(blockIdx.y + ty0) * GBM;

    // ldmatrix per-lane byte offsets (within a plane)
    // A x4 (per mb): m8k8 matrices [m0-7,klo][m8-15,klo][m0-7,khi][m8-15,khi]
    const uint32_t aoff = ((wm * 64 + (lane & 15)) * LDPH + (lane >> 4) * 8) * 2;
    // B x4 (per nb-pair): [n0-7,klo][n0-7,khi][n8-15,klo][n8-15,khi]
    const uint32_t boff = ((wn * 32 + (lane >> 4) * 8 + (lane & 7)) * LDPH
                           + ((lane >> 3) & 1) * 8) * 2;

    // X staging: 2 threads per row, 16 consecutive floats each
    const int xrow = tid >> 1;
    const int xcol = (tid & 1) * 16;
    const int gm   = (int)m0 + xrow;
    const float* Xp = X + ((size_t)(gm & 63) * TT + (gm >> 6)) * INN + xcol;

    const uint32_t bh_base = smb + (2 * PLANE_H) * 2;
    const uint32_t bl_base = smb + (3 * PLANE_H) * 2;

    float4 xa[4];
    auto gload = [&](int c) {
        const int k0 = c * GBK;
        #pragma unroll
        for (int i = 0; i < 4; i++)
            xa[i] = *(const float4*)(Xp + k0 + 4 * i);
    };
    auto wissue = [&](int c, int s) {
        const uint32_t soff = (uint32_t)s * STAGE_H * 2;
        #pragma unroll
        for (int i = 0; i < 2; i++) {
            const int sid = tid + i * 256;
            const int row = sid >> 2;
            const int seg = sid & 3;
            const uint32_t d = soff + (uint32_t)(row * LDPH * 2 + seg * 16);
            cp_async16(bh_base + d, g_Whi + (size_t)(n0 + row) * INN + c * GBK + seg * 8);
            cp_async16(bl_base + d, g_Wlo + (size_t)(n0 + row) * INN + c * GBK + seg * 8);
        }
    };
    auto sstore = [&](int s) {
        __half* Ah = smh + s * STAGE_H;
        __half* Al = Ah + PLANE_H;
        const int idx = xrow * LDPH + xcol;
        #pragma unroll
        for (int i = 0; i < 4; i++) {
            const float4 v = xa[i];
            const __half2 h0 = __floats2half2_rn(v.x, v.y);
            const __half2 h1 = __floats2half2_rn(v.z, v.w);
            const __half2 l0 = __floats2half2_rn(v.x - __low2float(h0),
                                                 v.y - __high2float(h0));
            const __half2 l1 = __floats2half2_rn(v.z - __low2float(h1),
                                                 v.w - __high2float(h1));
            *(__half2*)(Ah + idx + 4 * i)     = h0;
            *(__half2*)(Ah + idx + 4 * i + 2) = h1;
            *(__half2*)(Al + idx + 4 * i)     = l0;
            *(__half2*)(Al + idx + 4 * i + 2) = l1;
        }
    };

    float acc[4][4][4];
    #pragma unroll
    for (int i = 0; i < 4; i++)
        #pragma unroll
        for (int j = 0; j < 4; j++)
            #pragma unroll
            for (int q = 0; q < 4; q++) acc[i][j][q] = 0.0f;

    wissue(0, 0); cp_commit();
    gload(0);
    sstore(0);
    gload(1);
    cp_wait0();
    __syncthreads();

    for (int c = 0; c < NCHNK; c++) {
        const int cur = c & 1;
        if (c + 1 < NCHNK) {
            wissue(c + 1, 1 - cur);
            cp_commit();
            sstore(1 - cur);
        }
        if (c + 2 < NCHNK) gload(c + 2);

        const uint32_t stg = smb + (uint32_t)cur * STAGE_H * 2;
        const uint32_t Ah_b = stg;
        const uint32_t Al_b = stg + PLANE_H * 2;
        const uint32_t Bh_b = stg + 2 * PLANE_H * 2;
        const uint32_t Bl_b = stg + 3 * PLANE_H * 2;

        #pragma unroll
        for (int ks = 0; ks < 2; ks++) {
            const uint32_t kb = (uint32_t)ks * 32;   // 16 halfs

            // phase 1: ah + bh, hh products
            uint32_t ah[4][4], bh[4][2];
            #pragma unroll
            for (int mb = 0; mb < 4; mb++)
                LDSM_X4(ah[mb][0], ah[mb][1], ah[mb][2], ah[mb][3],
                        Ah_b + aoff + (uint32_t)(mb * 16 * LDPH * 2) + kb);
            #pragma unroll
            for (int np = 0; np < 2; np++)
                LDSM_X4(bh[2 * np][0], bh[2 * np][1],
                        bh[2 * np + 1][0], bh[2 * np + 1][1],
                        Bh_b + boff + (uint32_t)(np * 16 * LDPH * 2) + kb);
            #pragma unroll
            for (int mb = 0; mb < 4; mb++)
                #pragma unroll
                for (int nb = 0; nb < 4; nb++)
                    MMA_F16(acc[mb][nb], ah[mb], bh[nb]);

            // phase 2: bl, hl products
            {
                uint32_t bl[4][2];
                #pragma unroll
                for (int np = 0; np < 2; np++)
                    LDSM_X4(bl[2 * np][0], bl[2 * np][1],
                            bl[2 * np + 1][0], bl[2 * np + 1][1],
                            Bl_b + boff + (uint32_t)(np * 16 * LDPH * 2) + kb);
                #pragma unroll
                for (int mb = 0; mb < 4; mb++)
                    #pragma unroll
                    for (int nb = 0; nb < 4; nb++)
                        MMA_F16(acc[mb][nb], ah[mb], bl[nb]);
            }

            // phase 3: al, lh products (ah retired)
            {
                uint32_t al[4][4];
                #pragma unroll
                for (int mb = 0; mb < 4; mb++)
                    LDSM_X4(al[mb][0], al[mb][1], al[mb][2], al[mb][3],
                            Al_b + aoff + (uint32_t)(mb * 16 * LDPH * 2) + kb);
                #pragma unroll
                for (int mb = 0; mb < 4; mb++)
                    #pragma unroll
                    for (int nb = 0; nb < 4; nb++)
                        MMA_F16(acc[mb][nb], al[mb], bh[nb]);
            }
        }
        cp_wait0();
        __syncthreads();
    }

    #pragma unroll
    for (int mb = 0; mb < 4; mb++) {
        const size_t r = m0 + wm * 64 + mb * 16 + g;
        #pragma unroll
        for (int nb = 0; nb < 4; nb++) {
            const int col = n0 + wn * 32 + nb * 8 + tg * 2;
            *(float2*)(g_Wx + r * HH + col) =
                make_float2(acc[mb][nb][0], acc[mb][nb][1]);
            *(float2*)(g_Wx + (r + 8) * HH + col) =
                make_float2(acc[mb][nb][2], acc[mb][nb][3]);
        }
    }
}

// ---------------------------------------------------------------------------
// Kernel 2: recurrent scan chunk [t0, t1). Proven 512-thread internals;
//   ut/st/rec carried across chunks via __device__ globals.
// ---------------------------------------------------------------------------
__global__ void __launch_bounds__(512, 1) scan_kernel(
    const float* __restrict__ alpha,
    const float* __restrict__ ut0,
    const float* __restrict__ st0,
    const float* __restrict__ V,
    float* __restrict__ out,
    int t0, int t1, int first)
{
    const int b    = blockIdx.x;
    const int h    = threadIdx.x;
    const int lane = h & 31;
    const int wid  = h >> 5;

    __shared__ float    s_v[HH];
    __shared__ int      s_list[HH];
    __shared__ unsigned s_mask[16];

    const float a   = fminf(fmaxf(alpha[h], 0.81873075307798182f), 0.96078943915232320f);
    const float oma = 1.0f - a;
    const float vdiag = V[h * HH + h];

    float ut, st_prev, rec;
    if (first) {
        ut      = ut0[b * HH + h];
        st_prev = st0[b * HH + h];
        s_v[h] = st_prev;
        __syncthreads();
        float r0 = 0.f, r1 = 0.f, r2 = 0.f, r3 = 0.f;
        #pragma unroll 4
        for (int j = 0; j < HH; j += 4) {
            r0 = fmaf(s_v[j + 0], V[(j + 0) * HH + h], r0);
            r1 = fmaf(s_v[j + 1], V[(j + 1) * HH + h], r1);
            r2 = fmaf(s_v[j + 2], V[(j + 2) * HH + h], r2);
            r3 = fmaf(s_v[j + 3], V[(j + 3) * HH + h], r3);
        }
        rec = ((r0 + r1) + (r2 + r3)) - st_prev * vdiag;
    } else {
        ut      = g_ut [b * HH + h];
        st_prev = g_st [b * HH + h];
        rec     = g_rec[b * HH + h];
    }

    const size_t TSTRIDE = (size_t)64 * HH;
    const float* wxp = g_Wx + (size_t)b * HH + h;
    float*       op  = out  + (size_t)b * TT * HH + h;

    float wxb[8];
    #pragma unroll
    for (int i = 0; i < 8; i++) wxb[i] = __ldcs(wxp + (size_t)(t0 + i) * TSTRIDE);

    for (int tb = t0; tb < t1; tb += 8) {
        #pragma unroll
        for (int u = 0; u < 8; u++) {
            const int t = tb + u;
            const float wx = wxb[u];
            if (t + 8 < t1) wxb[u] = __ldcs(wxp + (size_t)(t + 8) * TSTRIDE);

            ut = a * (ut - st_prev) + oma * (wx + rec);
            const float st_new = (ut > 1.0f) ? 1.0f : 0.0f;
            __stcs(op + (size_t)t * HH, st_new);

            const bool fired = (st_new != 0.0f);
            const unsigned m = __ballot_sync(0xffffffffu, fired);
            if (lane == 0) s_mask[wid] = m;

            const int nf = __syncthreads_count(fired);   // barrier A
            if (nf == 0) { rec = 0.0f; st_prev = st_new; continue; }

            int off = 0;
            #pragma unroll
            for (int w = 0; w < 16; w++)
                off += (w < wid) ? __popc(s_mask[w]) : 0;
            if (fired)
                s_list[off + __popc(m & ((1u << lane) - 1u))] = h;
            __syncthreads();                              // barrier B

            float rr0 = 0.f, rr1 = 0.f, rr2 = 0.f, rr3 = 0.f;
            float rr4 = 0.f, rr5 = 0.f, rr6 = 0.f, rr7 = 0.f;
            int j = 0;
            for (; j + 8 <= nf; j += 8) {
                const int i0 = s_list[j + 0], i1 = s_list[j + 1];
                const int i2 = s_list[j + 2], i3 = s_list[j + 3];
                const int i4 = s_list[j + 4], i5 = s_list[j + 5];
                const int i6 = s_list[j + 6], i7 = s_list[j + 7];
                rr0 += __ldg(V + i0 * HH + h);
                rr1 += __ldg(V + i1 * HH + h);
                rr2 += __ldg(V + i2 * HH + h);
                rr3 += __ldg(V + i3 * HH + h);
                rr4 += __ldg(V + i4 * HH + h);
                rr5 += __ldg(V + i5 * HH + h);
                rr6 += __ldg(V + i6 * HH + h);
                rr7 += __ldg(V + i7 * HH + h);
            }
            for (; j < nf; j++) rr0 += __ldg(V + s_list[j] * HH + h);

            rec = (((rr0 + rr1) + (rr2 + rr3)) + ((rr4 + rr5) + (rr6 + rr7)))
                  - (fired ? vdiag : 0.0f);

            st_prev = st_new;
        }
    }

    g_ut [b * HH + h] = ut;
    g_st [b * HH + h] = st_prev;
    g_rec[b * HH + h] = rec;
}

// ---------------------------------------------------------------------------
// Launch: uneven t-chunks {232,232,232,232,72} -> short serial scan tail.
//   GEMM chunks alternate two streams; scan event-gated, high priority.
// ---------------------------------------------------------------------------
extern "C" void kernel_launch(void* const* d_in, const int* in_sizes, int n_in,
                              void* d_out, int out_size) {
    const float* x     = (const float*)d_in[0];
    const float* W     = (const float*)d_in[1];
    const float* V     = (const float*)d_in[2];
    const float* alpha = (const float*)d_in[3];
    const float* ut0   = (const float*)d_in[4];
    const float* st0   = (const float*)d_in[5];
    float* out = (float*)d_out;

    static const int tsplit[NCHUNKS_T + 1] = {0, 232, 464, 696, 928, 1000};

    static cudaStream_t sA = nullptr, sB = nullptr, sScan = nullptr;
    static cudaEvent_t  evPrep = nullptr, evG[NCHUNKS_T], evJoin = nullptr;
    if (!sA) {
        int lo, hi;
        cudaDeviceGetStreamPriorityRange(&lo, &hi);
        cudaStreamCreateWithFlags(&sA, cudaStreamNonBlocking);
        cudaStreamCreateWithFlags(&sB, cudaStreamNonBlocking);
        cudaStreamCreateWithPriority(&sScan, cudaStreamNonBlocking, hi);
        cudaEventCreateWithFlags(&evPrep, cudaEventDisableTiming);
        for (int k = 0; k < NCHUNKS_T; k++)
            cudaEventCreateWithFlags(&evG[k], cudaEventDisableTiming);
        cudaEventCreateWithFlags(&evJoin, cudaEventDisableTiming);
    }

    cudaFuncSetAttribute(gemm2fp16_kernel,
                         cudaFuncAttributeMaxDynamicSharedMemorySize, GEMM_SMEM);

    prep_w_kernel<<<(HH * INN + 255) / 256, 256>>>(W);
    cudaEventRecord(evPrep, 0);
    cudaStreamWaitEvent(sA, evPrep, 0);
    cudaStreamWaitEvent(sB, evPrep, 0);

    for (int k = 0; k < NCHUNKS_T; k++) {
        const int t0 = tsplit[k], t1 = tsplit[k + 1];
        const int ty0 = t0 / 2;
        const int mt  = (t1 - t0) / 2;
        cudaStream_t sg = (k & 1) ? sB : sA;
        dim3 ggrid(HH / GBN, mt);
        gemm2fp16_kernel<<<ggrid, 256, GEMM_SMEM, sg>>>(x, ty0);
        cudaEventRecord(evG[k], sg);

        cudaStreamWaitEvent(sScan, evG[k], 0);
        scan_kernel<<<BB, HH, 0, sScan>>>(alpha, ut0, st0, V, out,
                                          t0, t1, k == 0);
    }

    cudaEventRecord(evJoin, sScan);
    cudaStreamWaitEvent(0, evJoin, 0);
}